// round 9
// baseline (speedup 1.0000x reference)
#include <cuda_runtime.h>
#include <cooperative_groups.h>

namespace cg = cooperative_groups;

#define N_QUBITS 15
#define N_LAYERS 4
#define BATCHN   64
#define NLOC     16384            // per-CTA amplitudes (2^14)
#define NTHREADS 512
#define SMEM_BYTES (NLOC * sizeof(float2))   // 131072 B

// Exchange buffers: [batch][slot(2)][rank(2)][NLOC]  (double-buffered).
__device__ float2 g_xchg[BATCHN * 2 * 2 * NLOC];

// Bank swizzle: conflict-free for all three sweep patterns (verified:
// sweep A = const-XOR of consecutive; sweep B = bit4-disjoint half-groups;
// sweep C = full lane permutation).
__device__ __forceinline__ int SWZ(int i) { return i ^ ((i >> 5) & 31); }

// ---------------------------------------------------------------------------
// Factored rotation on register bit BIT (gate = scale * cheap-matrix; the
// scalar is accumulated once and applied to the final probabilities).
// tf = type*2 + form: type 0=RX 1=RY 2=RZ; form 0: t=s/c, form 1: u=c/s.
// 2 fma-pipe ops per amplitude.
// ---------------------------------------------------------------------------
template<int BIT>
__device__ __forceinline__ void rotfac(float2* a, float t, int tf) {
  if (tf == 0) {          // RX /c
#pragma unroll
    for (int j = 0; j < 32; j++) if (((j >> BIT) & 1) == 0) {
      const int k = j | (1 << BIT);
      float2 A0 = a[j], A1 = a[k];
      a[j].x = fmaf( t, A1.y, A0.x);  a[j].y = fmaf(-t, A1.x, A0.y);
      a[k].x = fmaf( t, A0.y, A1.x);  a[k].y = fmaf(-t, A0.x, A1.y);
    }
  } else if (tf == 1) {   // RX /s
#pragma unroll
    for (int j = 0; j < 32; j++) if (((j >> BIT) & 1) == 0) {
      const int k = j | (1 << BIT);
      float2 A0 = a[j], A1 = a[k];
      a[j].x = fmaf(t, A0.x,  A1.y);  a[j].y = fmaf(t, A0.y, -A1.x);
      a[k].x = fmaf(t, A1.x,  A0.y);  a[k].y = fmaf(t, A1.y, -A0.x);
    }
  } else if (tf == 2) {   // RY /c
#pragma unroll
    for (int j = 0; j < 32; j++) if (((j >> BIT) & 1) == 0) {
      const int k = j | (1 << BIT);
      float2 A0 = a[j], A1 = a[k];
      a[j].x = fmaf(-t, A1.x, A0.x);  a[j].y = fmaf(-t, A1.y, A0.y);
      a[k].x = fmaf( t, A0.x, A1.x);  a[k].y = fmaf( t, A0.y, A1.y);
    }
  } else if (tf == 3) {   // RY /s
#pragma unroll
    for (int j = 0; j < 32; j++) if (((j >> BIT) & 1) == 0) {
      const int k = j | (1 << BIT);
      float2 A0 = a[j], A1 = a[k];
      a[j].x = fmaf(t, A0.x, -A1.x);  a[j].y = fmaf(t, A0.y, -A1.y);
      a[k].x = fmaf(t, A1.x,  A0.x);  a[k].y = fmaf(t, A1.y,  A0.y);
    }
  } else if (tf == 4) {   // RZ /c
#pragma unroll
    for (int j = 0; j < 32; j++) if (((j >> BIT) & 1) == 0) {
      const int k = j | (1 << BIT);
      float2 A0 = a[j], A1 = a[k];
      a[j].x = fmaf( t, A0.y, A0.x);  a[j].y = fmaf(-t, A0.x, A0.y);
      a[k].x = fmaf(-t, A1.y, A1.x);  a[k].y = fmaf( t, A1.x, A1.y);
    }
  } else {                // RZ /s
#pragma unroll
    for (int j = 0; j < 32; j++) if (((j >> BIT) & 1) == 0) {
      const int k = j | (1 << BIT);
      float2 A0 = a[j], A1 = a[k];
      a[j].x = fmaf(t, A0.x,  A0.y);  a[j].y = fmaf(t, A0.y, -A0.x);
      a[k].x = fmaf(t, A1.x, -A1.y);  a[k].y = fmaf(t, A1.y,  A1.x);
    }
  }
}

template<int BC, int BT>
__device__ __forceinline__ void cnotl32(float2* a) {
#pragma unroll
  for (int j = 0; j < 32; j++) {
    if (((j >> BC) & 1) == 1 && ((j >> BT) & 1) == 0) {
      int k = j | (1 << BT);
      float2 t = a[j]; a[j] = a[k]; a[k] = t;
    }
  }
}

template<int BT>
__device__ __forceinline__ void xcond32(float2* a, bool c) {
#pragma unroll
  for (int j = 0; j < 32; j++) {
    if (((j >> BT) & 1) == 0) {
      int k = j | (1 << BT);
      float2 t0 = a[j], t1 = a[k];
      a[j] = c ? t1 : t0;
      a[k] = c ? t0 : t1;
    }
  }
}

// R_q0 applied to (mine m, partner o); my label = rank (labels are clean
// because CNOT(14,0) is applied physically via the fused load swap).
__device__ __forceinline__ float2 rot0_pair(float2 m, float2 o, float t,
                                            int f0, int rank) {
  float2 r;
  if (f0 == 0) {        // RX /c: m + t*J(o)
    r.x = fmaf( t, o.y, m.x);  r.y = fmaf(-t, o.x, m.y);
  } else if (f0 == 1) { // RX /s: u*m + J(o)
    r.x = fmaf(t, m.x,  o.y);  r.y = fmaf(t, m.y, -o.x);
  } else if (f0 == 2) { // RY /c
    float sg = rank ? t : -t;
    r.x = fmaf(sg, o.x, m.x);  r.y = fmaf(sg, o.y, m.y);
  } else {              // RY /s
    r.x = fmaf(t, m.x, rank ? o.x : -o.x);
    r.y = fmaf(t, m.y, rank ? o.y : -o.y);
  }
  return r;
}

__device__ __forceinline__ float2 rot0_diag(float2 m, float t, int f0, int rank) {
  float2 r;
  if (f0 == 4) {        // RZ /c: rank0: (1 - i t) m ; rank1: (1 + i t) m
    float tt = rank ? -t : t;
    r.x = fmaf( tt, m.y, m.x);  r.y = fmaf(-tt, m.x, m.y);
  } else {              // RZ /s: rank0: (u - i) m ; rank1: (u + i) m
    r.x = fmaf(t, m.x, rank ? -m.y : m.y);
    r.y = fmaf(t, m.y, rank ?  m.x : -m.x);
  }
  return r;
}

// Local amp index i: 14 bits; local bit k <-> qubit (14 - k) (qubits 1..14).
// Qubit 0 <-> cluster rank. Class = (q0 label, q1) = (rank-ish, local bit 13).
__global__ void __launch_bounds__(NTHREADS, 1) __cluster_dims__(2, 1, 1)
qdarts_kernel(const float* __restrict__ x, const float* __restrict__ Pm,
              const float* __restrict__ Qm, const float* __restrict__ rotp,
              const float* __restrict__ gum, float* __restrict__ out)
{
  extern __shared__ float2 SM[];   // NLOC float2, swizzled

  __shared__ float st_t[N_LAYERS * N_QUBITS];
  __shared__ int   st_f[N_LAYERS * N_QUBITS];
  __shared__ float st_s[N_LAYERS * N_QUBITS];
  __shared__ float sw[N_QUBITS][2];
  __shared__ float sred[4];
  __shared__ float sS2;

  cg::cluster_group cluster = cg::this_cluster();
  const int tid  = threadIdx.x;
  const int b    = blockIdx.x >> 1;
  const int rank = blockIdx.x & 1;

  // ---- Gate selection: argmax(P@Q + gumbel); store (t, variant, scale). ----
  if (tid < N_LAYERS * N_QUBITS) {
    const int ix = tid;
    float best = -1e30f; int gb = 0;
#pragma unroll
    for (int gg = 0; gg < 3; gg++) {
      float logit = 0.f;
#pragma unroll
      for (int k = 0; k < 4; k++)
        logit += Pm[ix * 4 + k] * Qm[(ix * 4 + k) * 3 + gg];
      float v = logit + gum[ix * 3 + gg];
      if (v > best) { best = v; gb = gg; }
    }
    float sv, cv;
    sincosf(0.5f * rotp[ix], &sv, &cv);
    const bool formB = fabsf(sv) > fabsf(cv);
    st_f[ix] = gb * 2 + (formB ? 1 : 0);
    st_t[ix] = formB ? __fdividef(cv, sv) : __fdividef(sv, cv);
    st_s[ix] = formB ? sv : cv;
  }
  if (tid < N_QUBITS) {
    float sv, cv;
    sincosf(0.5f * x[b * N_QUBITS + tid], &sv, &cv);
    sw[tid][0] = cv; sw[tid][1] = sv;
  }
  if (tid < 4) sred[tid] = 0.f;
  __syncthreads();

  if (tid == 0) {
    float pr = 1.f;
#pragma unroll 1
    for (int i = 0; i < N_LAYERS * N_QUBITS; i++) pr *= st_s[i];
    sS2 = pr * pr;
  }

  float ps0 = 0.f, ps1 = 0.f, ps2 = 0.f, ps3 = 0.f;

#pragma unroll 1
  for (int l = 0; l < N_LAYERS; l++) {
    const int g0 = l * N_QUBITS;
    float2 a[32];

    // ======== Sweep A: reg bits 13..9 (q1..q5), plus R_q0 ========
    {
      const float t0 = st_t[g0];
      const int   f0 = st_f[g0];
      if (l == 0) {
        // Analytic product state; both q0 branches available locally.
        float pref = 1.f;
#pragma unroll
        for (int q = 6; q < 15; q++) pref *= sw[q][(tid >> (14 - q)) & 1];
        const float m0 = pref * sw[0][rank];
        const float o0 = pref * sw[0][rank ^ 1];
#pragma unroll
        for (int j = 0; j < 32; j++) {
          float f = 1.f;
#pragma unroll
          for (int q = 1; q < 6; q++) f *= sw[q][(j >> (5 - q)) & 1];
          float2 m = make_float2(f * m0, 0.f);
          if (f0 >= 4) a[j] = rot0_diag(m, t0, f0, rank);
          else         a[j] = rot0_pair(m, make_float2(f * o0, 0.f), t0, f0, rank);
        }
      } else {
        // Partner half written by its previous copy pass (slot (l-1)&1).
        const float2* pg = g_xchg + ((size_t)(b * 2 + ((l - 1) & 1)) * 2
                                     + (rank ^ 1)) * NLOC;
        const bool odd = (tid & 1) != 0;   // amp bit0 = q14 (CNOT(14,0) ctrl)
        if (f0 >= 4) {   // RZ on q0: only odd amps crossed CTAs
#pragma unroll
          for (int j = 0; j < 32; j++) {
            const int i = (j << 9) | tid;
            float2 m = odd ? __ldcg(&pg[i]) : SM[SWZ(i)];
            a[j] = rot0_diag(m, t0, f0, rank);
          }
        } else {         // RX/RY: full pairing; fused CNOT(14,0) role swap
#pragma unroll
          for (int j = 0; j < 32; j++) {
            const int i = (j << 9) | tid;
            float2 own = SM[SWZ(i)];
            float2 p   = __ldcg(&pg[i]);
            float2 m = odd ? p : own;
            float2 o = odd ? own : p;
            a[j] = rot0_pair(m, o, t0, f0, rank);
          }
        }
      }
      // Rotations q1..q5 (reg bits 4..0)
      rotfac<4>(a, st_t[g0 + 1], st_f[g0 + 1]);
      rotfac<3>(a, st_t[g0 + 2], st_f[g0 + 2]);
      rotfac<2>(a, st_t[g0 + 3], st_f[g0 + 3]);
      rotfac<1>(a, st_t[g0 + 4], st_f[g0 + 4]);
      rotfac<0>(a, st_t[g0 + 5], st_f[g0 + 5]);
      // CNOT(0,1): control q0 label = rank (uniform) -> swap reg bit4.
      if (rank) {
#pragma unroll
        for (int j = 0; j < 16; j++) {
          float2 t2 = a[j]; a[j] = a[j | 16]; a[j | 16] = t2;
        }
      }
      cnotl32<4, 3>(a);  // CNOT(1,2)
      cnotl32<3, 2>(a);  // CNOT(2,3)
      cnotl32<2, 1>(a);  // CNOT(3,4)
      cnotl32<1, 0>(a);  // CNOT(4,5)
#pragma unroll
      for (int j = 0; j < 32; j++) SM[SWZ((j << 9) | tid)] = a[j];
    }
    __syncthreads();

    // ======== Sweep B: reg bits 8..4 (q6..q10) ========
    {
      const int hi5 = tid >> 4, lo4 = tid & 15;
#pragma unroll
      for (int j = 0; j < 32; j++)
        a[j] = SM[SWZ((hi5 << 9) | (j << 4) | lo4)];
      rotfac<4>(a, st_t[g0 + 6],  st_f[g0 + 6]);
      rotfac<3>(a, st_t[g0 + 7],  st_f[g0 + 7]);
      rotfac<2>(a, st_t[g0 + 8],  st_f[g0 + 8]);
      rotfac<1>(a, st_t[g0 + 9],  st_f[g0 + 9]);
      rotfac<0>(a, st_t[g0 + 10], st_f[g0 + 10]);
      xcond32<4>(a, (hi5 & 1) != 0);  // CNOT(5,6): ctrl q5 = local bit9
      cnotl32<4, 3>(a);  // CNOT(6,7)
      cnotl32<3, 2>(a);  // CNOT(7,8)
      cnotl32<2, 1>(a);  // CNOT(8,9)
      cnotl32<1, 0>(a);  // CNOT(9,10)
#pragma unroll
      for (int j = 0; j < 32; j++)
        SM[SWZ((hi5 << 9) | (j << 4) | lo4)] = a[j];
    }
    __syncthreads();

    // ======== Sweep C: reg bits 4..0 (q10..q14; rotations q11..q14) ========
    {
#pragma unroll
      for (int j = 0; j < 32; j++) a[j] = SM[SWZ((tid << 5) | j)];
      rotfac<3>(a, st_t[g0 + 11], st_f[g0 + 11]);
      rotfac<2>(a, st_t[g0 + 12], st_f[g0 + 12]);
      rotfac<1>(a, st_t[g0 + 13], st_f[g0 + 13]);
      rotfac<0>(a, st_t[g0 + 14], st_f[g0 + 14]);
      cnotl32<4, 3>(a);  // CNOT(10,11)
      cnotl32<3, 2>(a);  // CNOT(11,12)
      cnotl32<2, 1>(a);  // CNOT(12,13)
      cnotl32<1, 0>(a);  // CNOT(13,14)
      // CNOT(14,0): physical, fused into next layer's sweep-A loads
      // (or into the class remap below for the last layer).

      if (l < N_LAYERS - 1) {
#pragma unroll
        for (int j = 0; j < 32; j++) SM[SWZ((tid << 5) | j)] = a[j];
        __syncthreads();
        // Coalesced copy pass SMEM -> gmem (slot l&1) for partner.
        float2* xw = g_xchg + ((size_t)(b * 2 + (l & 1)) * 2 + rank) * NLOC;
#pragma unroll
        for (int k = 0; k < 32; k++) {
          const int i = (k << 9) | tid;
          xw[i] = SM[SWZ(i)];
        }
        cluster.sync();
      } else {
        // Fold CNOT(14,0) + |amp|^2 class reduction.
        // i = (tid<<5)|j: amp bit0 = j&1 (q14, the CNOT control);
        // q1 = local bit13 = tid bit8.  Odd amps belong to class MSB rank^1.
        float pe = 0.f, po = 0.f;
#pragma unroll
        for (int j = 0; j < 32; j++) {
          float p = fmaf(a[j].x, a[j].x, a[j].y * a[j].y);
          if (j & 1) po += p; else pe += p;
        }
        const int b13 = (tid >> 8) & 1;
        const int ce = rank * 2 + b13;          // even-j class
        const int co = (rank ^ 1) * 2 + b13;    // odd-j class
        ps0 = pe; ps1 = po; ps2 = (float)ce; ps3 = (float)co;
      }
    }
  }

  // ---- Reduce class sums: warp -> CTA shared -> cross-CTA (DSMEM) ----
  {
    float pe = ps0, po = ps1;
    const int ce = (int)ps2, co = (int)ps3;   // warp-uniform
#pragma unroll
    for (int o = 16; o > 0; o >>= 1) {
      pe += __shfl_xor_sync(0xffffffffu, pe, o);
      po += __shfl_xor_sync(0xffffffffu, po, o);
    }
    if ((tid & 31) == 0) {
      atomicAdd(&sred[ce], pe);
      atomicAdd(&sred[co], po);
    }
  }
  __syncthreads();

  if (rank == 1 && tid < 4) {
    float* dst = cluster.map_shared_rank(sred, 0);
    atomicAdd(dst + tid, sred[tid]);
  }
  cluster.sync();
  if (rank == 0 && tid < 4) out[b * 4 + tid] = sred[tid] * sS2;
}

extern "C" void kernel_launch(void* const* d_in, const int* in_sizes, int n_in,
                              void* d_out, int out_size) {
  const float* x    = (const float*)d_in[0];
  const float* P    = (const float*)d_in[1];
  const float* Q    = (const float*)d_in[2];
  const float* rotp = (const float*)d_in[3];
  const float* gum  = (const float*)d_in[4];
  cudaFuncSetAttribute(qdarts_kernel,
                       cudaFuncAttributeMaxDynamicSharedMemorySize,
                       (int)SMEM_BYTES);
  qdarts_kernel<<<BATCHN * 2, NTHREADS, SMEM_BYTES>>>(x, P, Q, rotp, gum,
                                                      (float*)d_out);
}

// round 10
// speedup vs baseline: 1.0861x; 1.0861x over previous
#include <cuda_runtime.h>
#include <cooperative_groups.h>

namespace cg = cooperative_groups;

#define N_QUBITS 15
#define N_LAYERS 4
#define BATCHN   64
#define NLOC     16384            // per-CTA amplitudes (2^14)
#define NTHREADS 512
#define SMEM_BYTES (NLOC * sizeof(float2))   // 131072 B

// Exchange buffers: [batch][slot(2)][rank(2)][NLOC]  (double-buffered).
__device__ float2 g_xchg[BATCHN * 2 * 2 * NLOC];

// ---------------------------------------------------------------------------
// Factored rotation on register bit BIT (gate = scale * cheap-matrix; the
// scalar is accumulated once and applied to the final probabilities).
// tf = type*2 + form: type 0=RX 1=RY 2=RZ; form 0: t=s/c, form 1: u=c/s.
// ---------------------------------------------------------------------------
template<int BIT>
__device__ __forceinline__ void rotfac(float2* a, float t, int tf) {
  if (tf == 0) {          // RX /c
#pragma unroll
    for (int j = 0; j < 32; j++) if (((j >> BIT) & 1) == 0) {
      const int k = j | (1 << BIT);
      float2 A0 = a[j], A1 = a[k];
      a[j].x = fmaf( t, A1.y, A0.x);  a[j].y = fmaf(-t, A1.x, A0.y);
      a[k].x = fmaf( t, A0.y, A1.x);  a[k].y = fmaf(-t, A0.x, A1.y);
    }
  } else if (tf == 1) {   // RX /s
#pragma unroll
    for (int j = 0; j < 32; j++) if (((j >> BIT) & 1) == 0) {
      const int k = j | (1 << BIT);
      float2 A0 = a[j], A1 = a[k];
      a[j].x = fmaf(t, A0.x,  A1.y);  a[j].y = fmaf(t, A0.y, -A1.x);
      a[k].x = fmaf(t, A1.x,  A0.y);  a[k].y = fmaf(t, A1.y, -A0.x);
    }
  } else if (tf == 2) {   // RY /c
#pragma unroll
    for (int j = 0; j < 32; j++) if (((j >> BIT) & 1) == 0) {
      const int k = j | (1 << BIT);
      float2 A0 = a[j], A1 = a[k];
      a[j].x = fmaf(-t, A1.x, A0.x);  a[j].y = fmaf(-t, A1.y, A0.y);
      a[k].x = fmaf( t, A0.x, A1.x);  a[k].y = fmaf( t, A0.y, A1.y);
    }
  } else if (tf == 3) {   // RY /s
#pragma unroll
    for (int j = 0; j < 32; j++) if (((j >> BIT) & 1) == 0) {
      const int k = j | (1 << BIT);
      float2 A0 = a[j], A1 = a[k];
      a[j].x = fmaf(t, A0.x, -A1.x);  a[j].y = fmaf(t, A0.y, -A1.y);
      a[k].x = fmaf(t, A1.x,  A0.x);  a[k].y = fmaf(t, A1.y,  A0.y);
    }
  } else if (tf == 4) {   // RZ /c
#pragma unroll
    for (int j = 0; j < 32; j++) if (((j >> BIT) & 1) == 0) {
      const int k = j | (1 << BIT);
      float2 A0 = a[j], A1 = a[k];
      a[j].x = fmaf( t, A0.y, A0.x);  a[j].y = fmaf(-t, A0.x, A0.y);
      a[k].x = fmaf(-t, A1.y, A1.x);  a[k].y = fmaf( t, A1.x, A1.y);
    }
  } else {                // RZ /s
#pragma unroll
    for (int j = 0; j < 32; j++) if (((j >> BIT) & 1) == 0) {
      const int k = j | (1 << BIT);
      float2 A0 = a[j], A1 = a[k];
      a[j].x = fmaf(t, A0.x,  A0.y);  a[j].y = fmaf(t, A0.y, -A0.x);
      a[k].x = fmaf(t, A1.x, -A1.y);  a[k].y = fmaf(t, A1.y,  A1.x);
    }
  }
}

// Factored rotation on a lane-bit qubit (amp bit = lane bit LB).
template<int LB>
__device__ __forceinline__ void rot_lane_fac(float2* a, float t, int tf, int lane) {
  const int cb = (lane >> LB) & 1;
  if (tf == 0) {          // RX /c: r = m + t J(p)
#pragma unroll
    for (int j = 0; j < 32; j++) {
      float px = __shfl_xor_sync(0xffffffffu, a[j].x, 1 << LB);
      float py = __shfl_xor_sync(0xffffffffu, a[j].y, 1 << LB);
      float nx = fmaf( t, py, a[j].x);
      float ny = fmaf(-t, px, a[j].y);
      a[j].x = nx; a[j].y = ny;
    }
  } else if (tf == 1) {   // RX /s: r = u m + J(p)
#pragma unroll
    for (int j = 0; j < 32; j++) {
      float px = __shfl_xor_sync(0xffffffffu, a[j].x, 1 << LB);
      float py = __shfl_xor_sync(0xffffffffu, a[j].y, 1 << LB);
      a[j].x = fmaf(t, a[j].x,  py);
      a[j].y = fmaf(t, a[j].y, -px);
    }
  } else if (tf == 2) {   // RY /c: r = m + sg p, sg = cb? t : -t
    const float sg = cb ? t : -t;
#pragma unroll
    for (int j = 0; j < 32; j++) {
      float px = __shfl_xor_sync(0xffffffffu, a[j].x, 1 << LB);
      float py = __shfl_xor_sync(0xffffffffu, a[j].y, 1 << LB);
      a[j].x = fmaf(sg, px, a[j].x);
      a[j].y = fmaf(sg, py, a[j].y);
    }
  } else if (tf == 3) {   // RY /s: r = u m + (cb? p : -p)
#pragma unroll
    for (int j = 0; j < 32; j++) {
      float px = __shfl_xor_sync(0xffffffffu, a[j].x, 1 << LB);
      float py = __shfl_xor_sync(0xffffffffu, a[j].y, 1 << LB);
      a[j].x = fmaf(t, a[j].x, cb ? px : -px);
      a[j].y = fmaf(t, a[j].y, cb ? py : -py);
    }
  } else if (tf == 4) {   // RZ /c: diagonal, no shfl
    const float tt = cb ? -t : t;
#pragma unroll
    for (int j = 0; j < 32; j++) {
      float nx = fmaf( tt, a[j].y, a[j].x);
      float ny = fmaf(-tt, a[j].x, a[j].y);
      a[j].x = nx; a[j].y = ny;
    }
  } else {                // RZ /s: diagonal, no shfl
#pragma unroll
    for (int j = 0; j < 32; j++) {
      float nx = fmaf(t, a[j].x, cb ? -a[j].y : a[j].y);
      float ny = fmaf(t, a[j].y, cb ?  a[j].x : -a[j].x);
      a[j].x = nx; a[j].y = ny;
    }
  }
}

template<int BC, int BT>
__device__ __forceinline__ void cnotl32(float2* a) {
#pragma unroll
  for (int j = 0; j < 32; j++) {
    if (((j >> BC) & 1) == 1 && ((j >> BT) & 1) == 0) {
      int k = j | (1 << BT);
      float2 t = a[j]; a[j] = a[k]; a[k] = t;
    }
  }
}

template<int BT>
__device__ __forceinline__ void xcond32(float2* a, bool c) {
#pragma unroll
  for (int j = 0; j < 32; j++) {
    if (((j >> BT) & 1) == 0) {
      int k = j | (1 << BT);
      float2 t0 = a[j], t1 = a[k];
      a[j] = c ? t1 : t0;
      a[k] = c ? t0 : t1;
    }
  }
}

// R_q0 applied to (mine m, partner o); my label = rank.
__device__ __forceinline__ float2 rot0_pair(float2 m, float2 o, float t,
                                            int f0, int rank) {
  float2 r;
  if (f0 == 0) {        // RX /c
    r.x = fmaf( t, o.y, m.x);  r.y = fmaf(-t, o.x, m.y);
  } else if (f0 == 1) { // RX /s
    r.x = fmaf(t, m.x,  o.y);  r.y = fmaf(t, m.y, -o.x);
  } else if (f0 == 2) { // RY /c
    float sg = rank ? t : -t;
    r.x = fmaf(sg, o.x, m.x);  r.y = fmaf(sg, o.y, m.y);
  } else {              // RY /s
    r.x = fmaf(t, m.x, rank ? o.x : -o.x);
    r.y = fmaf(t, m.y, rank ? o.y : -o.y);
  }
  return r;
}

__device__ __forceinline__ float2 rot0_diag(float2 m, float t, int f0, int rank) {
  float2 r;
  if (f0 == 4) {        // RZ /c
    float tt = rank ? -t : t;
    r.x = fmaf( tt, m.y, m.x);  r.y = fmaf(-tt, m.x, m.y);
  } else {              // RZ /s
    r.x = fmaf(t, m.x, rank ? -m.y : m.y);
    r.y = fmaf(t, m.y, rank ?  m.x : -m.x);
  }
  return r;
}

// Local amp index i: 14 bits; local bit k <-> qubit (14 - k) (qubits 1..14).
// Qubit 0 <-> cluster rank. Class = (q0 label, q1).
__global__ void __launch_bounds__(NTHREADS, 1) __cluster_dims__(2, 1, 1)
qdarts_kernel(const float* __restrict__ x, const float* __restrict__ Pm,
              const float* __restrict__ Qm, const float* __restrict__ rotp,
              const float* __restrict__ gum, float* __restrict__ out)
{
  extern __shared__ float2 SM[];   // NLOC float2, LINEAR layout

  __shared__ float st_t[N_LAYERS * N_QUBITS];
  __shared__ int   st_f[N_LAYERS * N_QUBITS];
  __shared__ float st_s[N_LAYERS * N_QUBITS];
  __shared__ float sw[N_QUBITS][2];
  __shared__ float sred[4];
  __shared__ float sS2;

  cg::cluster_group cluster = cg::this_cluster();
  const int tid  = threadIdx.x;
  const int b    = blockIdx.x >> 1;
  const int rank = blockIdx.x & 1;
  const int lane = tid & 31;

  // ---- Gate selection: argmax(P@Q + gumbel); store (t, variant, scale). ----
  if (tid < N_LAYERS * N_QUBITS) {
    const int ix = tid;
    float best = -1e30f; int gb = 0;
#pragma unroll
    for (int gg = 0; gg < 3; gg++) {
      float logit = 0.f;
#pragma unroll
      for (int k = 0; k < 4; k++)
        logit += Pm[ix * 4 + k] * Qm[(ix * 4 + k) * 3 + gg];
      float v = logit + gum[ix * 3 + gg];
      if (v > best) { best = v; gb = gg; }
    }
    float sv, cv;
    sincosf(0.5f * rotp[ix], &sv, &cv);
    const bool formB = fabsf(sv) > fabsf(cv);
    st_f[ix] = gb * 2 + (formB ? 1 : 0);
    st_t[ix] = formB ? __fdividef(cv, sv) : __fdividef(sv, cv);
    st_s[ix] = formB ? sv : cv;
  }
  if (tid < N_QUBITS) {
    float sv, cv;
    sincosf(0.5f * x[b * N_QUBITS + tid], &sv, &cv);
    sw[tid][0] = cv; sw[tid][1] = sv;
  }
  if (tid < 4) sred[tid] = 0.f;
  __syncthreads();

  if (tid == 0) {
    float pr = 1.f;
#pragma unroll 1
    for (int i = 0; i < N_LAYERS * N_QUBITS; i++) pr *= st_s[i];
    sS2 = pr * pr;
  }

  // Composed lane permutation for CNOT chain (11,12)(12,13)(13,14) on lane
  // bits 3..0 (q11..q14); src = F^{-1}(lane) applying last-CNOT first.
  int t_ = lane;
  t_ ^= ((t_ >> 1) & 1);        // C(13,14): bit0 ^= bit1
  t_ ^= ((t_ >> 2) & 1) << 1;   // C(12,13): bit1 ^= bit2
  t_ ^= ((t_ >> 3) & 1) << 2;   // C(11,12): bit2 ^= bit3
  const int srcE = t_;
  const int srcO = t_ ^ 8;      // C(10,11): ctrl q10 = reg bit0 (odd j)

  float ps = 0.f; int pcls = 0;

#pragma unroll 1
  for (int l = 0; l < N_LAYERS; l++) {
    const int g0 = l * N_QUBITS;
    float2 a[32];

    // ======== Sweep A: amp = (j<<9)|tid; reg j = amp bits 13..9 (q1..q5) ====
    {
      const float t0 = st_t[g0];
      const int   f0 = st_f[g0];
      if (l == 0) {
        float pref = 1.f;
#pragma unroll
        for (int q = 6; q < 15; q++) pref *= sw[q][(tid >> (14 - q)) & 1];
        const float m0 = pref * sw[0][rank];
        const float o0 = pref * sw[0][rank ^ 1];
#pragma unroll
        for (int j = 0; j < 32; j++) {
          float f = 1.f;
#pragma unroll
          for (int q = 1; q < 6; q++) f *= sw[q][(j >> (5 - q)) & 1];
          float2 m = make_float2(f * m0, 0.f);
          if (f0 >= 4) a[j] = rot0_diag(m, t0, f0, rank);
          else         a[j] = rot0_pair(m, make_float2(f * o0, 0.f), t0, f0, rank);
        }
      } else {
        const float2* pg = g_xchg + ((size_t)(b * 2 + ((l - 1) & 1)) * 2
                                     + (rank ^ 1)) * NLOC;
        const bool odd = (tid & 1) != 0;   // amp bit0 = q14 (CNOT(14,0) ctrl)
        if (f0 >= 4) {   // RZ on q0: only odd amps crossed CTAs
#pragma unroll
          for (int j = 0; j < 32; j++) {
            const int i = (j << 9) | tid;
            float2 m = odd ? __ldcg(&pg[i]) : SM[i];
            a[j] = rot0_diag(m, t0, f0, rank);
          }
        } else {         // RX/RY: full pairing; fused CNOT(14,0) role swap
#pragma unroll
          for (int j = 0; j < 32; j++) {
            const int i = (j << 9) | tid;
            float2 own = SM[i];
            float2 p   = __ldcg(&pg[i]);
            float2 m = odd ? p : own;
            float2 o = odd ? own : p;
            a[j] = rot0_pair(m, o, t0, f0, rank);
          }
        }
      }
      rotfac<4>(a, st_t[g0 + 1], st_f[g0 + 1]);  // R_q1
      rotfac<3>(a, st_t[g0 + 2], st_f[g0 + 2]);  // R_q2
      rotfac<2>(a, st_t[g0 + 3], st_f[g0 + 3]);  // R_q3
      rotfac<1>(a, st_t[g0 + 4], st_f[g0 + 4]);  // R_q4
      rotfac<0>(a, st_t[g0 + 5], st_f[g0 + 5]);  // R_q5
      // CNOT(0,1): ctrl q0 = rank (uniform) -> swap reg bit4.
      if (rank) {
#pragma unroll
        for (int j = 0; j < 16; j++) {
          float2 t2 = a[j]; a[j] = a[j | 16]; a[j | 16] = t2;
        }
      }
      cnotl32<4, 3>(a);  // CNOT(1,2)
      cnotl32<3, 2>(a);  // CNOT(2,3)
      cnotl32<2, 1>(a);  // CNOT(3,4)
      cnotl32<1, 0>(a);  // CNOT(4,5)
      // CNOT(5,6) deferred to sweep B (target q6 not local).
#pragma unroll
      for (int j = 0; j < 32; j++) SM[(j << 9) | tid] = a[j];
    }
    __syncthreads();

    // ======== Sweep B: amp = (hi5<<9)|(j<<4)|lo4 ========
    // reg j = amp bits 8..4 (q6..q10); lane bits 3..0 = amp bits 3..0 (q11..14).
    {
      const int hi5 = tid >> 4, lo4 = tid & 15;
      const int base = (hi5 << 9) | lo4;
#pragma unroll
      for (int j = 0; j < 32; j++) a[j] = SM[base | (j << 4)];
      // Rotations q6..q10 (register bits 4..0)
      rotfac<4>(a, st_t[g0 + 6],  st_f[g0 + 6]);
      rotfac<3>(a, st_t[g0 + 7],  st_f[g0 + 7]);
      rotfac<2>(a, st_t[g0 + 8],  st_f[g0 + 8]);
      rotfac<1>(a, st_t[g0 + 9],  st_f[g0 + 9]);
      rotfac<0>(a, st_t[g0 + 10], st_f[g0 + 10]);
      // Rotations q11..q14 (lane bits 3..0)
      rot_lane_fac<3>(a, st_t[g0 + 11], st_f[g0 + 11], lane);
      rot_lane_fac<2>(a, st_t[g0 + 12], st_f[g0 + 12], lane);
      rot_lane_fac<1>(a, st_t[g0 + 13], st_f[g0 + 13], lane);
      rot_lane_fac<0>(a, st_t[g0 + 14], st_f[g0 + 14], lane);
      // CNOT(5,6): ctrl q5 = amp bit9 = hi5 bit0; target q6 = reg bit4.
      xcond32<4>(a, (hi5 & 1) != 0);
      cnotl32<4, 3>(a);  // CNOT(6,7)
      cnotl32<3, 2>(a);  // CNOT(7,8)
      cnotl32<2, 1>(a);  // CNOT(8,9)
      cnotl32<1, 0>(a);  // CNOT(9,10)
      // CNOT(10,11)+(11,12)+(12,13)+(13,14): one composed lane permutation.
#pragma unroll
      for (int j = 0; j < 32; j++) {
        const int src = (j & 1) ? srcO : srcE;
        a[j].x = __shfl_sync(0xffffffffu, a[j].x, src);
        a[j].y = __shfl_sync(0xffffffffu, a[j].y, src);
      }
      // CNOT(14,0): physical, fused into next layer's sweep-A loads
      // (or into the class remap below for the last layer).

      if (l < N_LAYERS - 1) {
        float2* xw = g_xchg + ((size_t)(b * 2 + (l & 1)) * 2 + rank) * NLOC;
#pragma unroll
        for (int j = 0; j < 32; j++) {
          const int i = base | (j << 4);
          SM[i] = a[j];
          xw[i] = a[j];
        }
        cluster.sync();
      } else {
        // |amp|^2 class reduction with CNOT(14,0) fold.
        // ctrl q14 = amp bit0 = lane bit0 (thread-uniform over its 32 regs);
        // class = (q0 label, q1) ; q1 = amp bit13 = tid bit8.
        float p = 0.f;
#pragma unroll
        for (int j = 0; j < 32; j++)
          p = fmaf(a[j].x, a[j].x, fmaf(a[j].y, a[j].y, p));
        ps = p;
        pcls = ((((lane & 1) ? (rank ^ 1) : rank) << 1) | ((tid >> 8) & 1));
      }
    }
  }

  // ---- Reduce: parity-preserving warp reduce -> CTA shared -> cross-CTA ----
#pragma unroll
  for (int o = 16; o >= 2; o >>= 1)
    ps += __shfl_xor_sync(0xffffffffu, ps, o);
  if (lane < 2) atomicAdd(&sred[pcls], ps);
  __syncthreads();

  if (rank == 1 && tid < 4) {
    float* dst = cluster.map_shared_rank(sred, 0);
    atomicAdd(dst + tid, sred[tid]);
  }
  cluster.sync();
  if (rank == 0 && tid < 4) out[b * 4 + tid] = sred[tid] * sS2;
}

extern "C" void kernel_launch(void* const* d_in, const int* in_sizes, int n_in,
                              void* d_out, int out_size) {
  const float* x    = (const float*)d_in[0];
  const float* P    = (const float*)d_in[1];
  const float* Q    = (const float*)d_in[2];
  const float* rotp = (const float*)d_in[3];
  const float* gum  = (const float*)d_in[4];
  cudaFuncSetAttribute(qdarts_kernel,
                       cudaFuncAttributeMaxDynamicSharedMemorySize,
                       (int)SMEM_BYTES);
  qdarts_kernel<<<BATCHN * 2, NTHREADS, SMEM_BYTES>>>(x, P, Q, rotp, gum,
                                                      (float*)d_out);
}

// round 11
// speedup vs baseline: 1.1417x; 1.0512x over previous
#include <cuda_runtime.h>
#include <cooperative_groups.h>

namespace cg = cooperative_groups;

#define N_QUBITS 15
#define N_LAYERS 4
#define BATCHN   64
#define NLOC     16384            // per-CTA amplitudes (2^14)
#define NTHREADS 1024
#define SMEM_BYTES (NLOC * sizeof(float2))   // 131072 B

// Exchange buffers: [batch][slot(2)][rank(2)][NLOC]  (double-buffered).
__device__ float2 g_xchg[BATCHN * 2 * 2 * NLOC];

// ---------------------------------------------------------------------------
// Factored rotation on register bit BIT of a 16-amp subcube.
// tf = type*2 + form: type 0=RX 1=RY 2=RZ; form 0: t=s/c, form 1: u=c/s.
// ---------------------------------------------------------------------------
template<int BIT>
__device__ __forceinline__ void rotfac16(float2* a, float t, int tf) {
  if (tf == 0) {          // RX /c
#pragma unroll
    for (int j = 0; j < 16; j++) if (((j >> BIT) & 1) == 0) {
      const int k = j | (1 << BIT);
      float2 A0 = a[j], A1 = a[k];
      a[j].x = fmaf( t, A1.y, A0.x);  a[j].y = fmaf(-t, A1.x, A0.y);
      a[k].x = fmaf( t, A0.y, A1.x);  a[k].y = fmaf(-t, A0.x, A1.y);
    }
  } else if (tf == 1) {   // RX /s
#pragma unroll
    for (int j = 0; j < 16; j++) if (((j >> BIT) & 1) == 0) {
      const int k = j | (1 << BIT);
      float2 A0 = a[j], A1 = a[k];
      a[j].x = fmaf(t, A0.x,  A1.y);  a[j].y = fmaf(t, A0.y, -A1.x);
      a[k].x = fmaf(t, A1.x,  A0.y);  a[k].y = fmaf(t, A1.y, -A0.x);
    }
  } else if (tf == 2) {   // RY /c
#pragma unroll
    for (int j = 0; j < 16; j++) if (((j >> BIT) & 1) == 0) {
      const int k = j | (1 << BIT);
      float2 A0 = a[j], A1 = a[k];
      a[j].x = fmaf(-t, A1.x, A0.x);  a[j].y = fmaf(-t, A1.y, A0.y);
      a[k].x = fmaf( t, A0.x, A1.x);  a[k].y = fmaf( t, A0.y, A1.y);
    }
  } else if (tf == 3) {   // RY /s
#pragma unroll
    for (int j = 0; j < 16; j++) if (((j >> BIT) & 1) == 0) {
      const int k = j | (1 << BIT);
      float2 A0 = a[j], A1 = a[k];
      a[j].x = fmaf(t, A0.x, -A1.x);  a[j].y = fmaf(t, A0.y, -A1.y);
      a[k].x = fmaf(t, A1.x,  A0.x);  a[k].y = fmaf(t, A1.y,  A0.y);
    }
  } else if (tf == 4) {   // RZ /c
#pragma unroll
    for (int j = 0; j < 16; j++) if (((j >> BIT) & 1) == 0) {
      const int k = j | (1 << BIT);
      float2 A0 = a[j], A1 = a[k];
      a[j].x = fmaf( t, A0.y, A0.x);  a[j].y = fmaf(-t, A0.x, A0.y);
      a[k].x = fmaf(-t, A1.y, A1.x);  a[k].y = fmaf( t, A1.x, A1.y);
    }
  } else {                // RZ /s
#pragma unroll
    for (int j = 0; j < 16; j++) if (((j >> BIT) & 1) == 0) {
      const int k = j | (1 << BIT);
      float2 A0 = a[j], A1 = a[k];
      a[j].x = fmaf(t, A0.x,  A0.y);  a[j].y = fmaf(t, A0.y, -A0.x);
      a[k].x = fmaf(t, A1.x, -A1.y);  a[k].y = fmaf(t, A1.y,  A1.x);
    }
  }
}

// Factored rotation on a lane-bit qubit (amp bit = lane bit LB), 16 regs.
template<int LB>
__device__ __forceinline__ void rot_lane_fac16(float2* a, float t, int tf, int lane) {
  const int cb = (lane >> LB) & 1;
  if (tf == 0) {          // RX /c
#pragma unroll
    for (int j = 0; j < 16; j++) {
      float px = __shfl_xor_sync(0xffffffffu, a[j].x, 1 << LB);
      float py = __shfl_xor_sync(0xffffffffu, a[j].y, 1 << LB);
      float nx = fmaf( t, py, a[j].x);
      float ny = fmaf(-t, px, a[j].y);
      a[j].x = nx; a[j].y = ny;
    }
  } else if (tf == 1) {   // RX /s
#pragma unroll
    for (int j = 0; j < 16; j++) {
      float px = __shfl_xor_sync(0xffffffffu, a[j].x, 1 << LB);
      float py = __shfl_xor_sync(0xffffffffu, a[j].y, 1 << LB);
      a[j].x = fmaf(t, a[j].x,  py);
      a[j].y = fmaf(t, a[j].y, -px);
    }
  } else if (tf == 2) {   // RY /c
    const float sg = cb ? t : -t;
#pragma unroll
    for (int j = 0; j < 16; j++) {
      float px = __shfl_xor_sync(0xffffffffu, a[j].x, 1 << LB);
      float py = __shfl_xor_sync(0xffffffffu, a[j].y, 1 << LB);
      a[j].x = fmaf(sg, px, a[j].x);
      a[j].y = fmaf(sg, py, a[j].y);
    }
  } else if (tf == 3) {   // RY /s
#pragma unroll
    for (int j = 0; j < 16; j++) {
      float px = __shfl_xor_sync(0xffffffffu, a[j].x, 1 << LB);
      float py = __shfl_xor_sync(0xffffffffu, a[j].y, 1 << LB);
      a[j].x = fmaf(t, a[j].x, cb ? px : -px);
      a[j].y = fmaf(t, a[j].y, cb ? py : -py);
    }
  } else if (tf == 4) {   // RZ /c: diagonal, no shfl
    const float tt = cb ? -t : t;
#pragma unroll
    for (int j = 0; j < 16; j++) {
      float nx = fmaf( tt, a[j].y, a[j].x);
      float ny = fmaf(-tt, a[j].x, a[j].y);
      a[j].x = nx; a[j].y = ny;
    }
  } else {                // RZ /s: diagonal, no shfl
#pragma unroll
    for (int j = 0; j < 16; j++) {
      float nx = fmaf(t, a[j].x, cb ? -a[j].y : a[j].y);
      float ny = fmaf(t, a[j].y, cb ?  a[j].x : -a[j].x);
      a[j].x = nx; a[j].y = ny;
    }
  }
}

template<int BC, int BT>
__device__ __forceinline__ void cnotl16(float2* a) {
#pragma unroll
  for (int j = 0; j < 16; j++) {
    if (((j >> BC) & 1) == 1 && ((j >> BT) & 1) == 0) {
      int k = j | (1 << BT);
      float2 t = a[j]; a[j] = a[k]; a[k] = t;
    }
  }
}

template<int BT>
__device__ __forceinline__ void xcond16(float2* a, bool c) {
#pragma unroll
  for (int j = 0; j < 16; j++) {
    if (((j >> BT) & 1) == 0) {
      int k = j | (1 << BT);
      float2 t0 = a[j], t1 = a[k];
      a[j] = c ? t1 : t0;
      a[k] = c ? t0 : t1;
    }
  }
}

// Generic factored pair rotation: m = value with qubit label lbl, o = partner
// (label lbl^1); returns new value at label lbl.
__device__ __forceinline__ float2 rotp(float2 m, float2 o, float t,
                                       int f, int lbl) {
  float2 r;
  if (f == 0) {        // RX /c
    r.x = fmaf( t, o.y, m.x);  r.y = fmaf(-t, o.x, m.y);
  } else if (f == 1) { // RX /s
    r.x = fmaf(t, m.x,  o.y);  r.y = fmaf(t, m.y, -o.x);
  } else if (f == 2) { // RY /c
    float sg = lbl ? t : -t;
    r.x = fmaf(sg, o.x, m.x);  r.y = fmaf(sg, o.y, m.y);
  } else {             // RY /s
    r.x = fmaf(t, m.x, lbl ? o.x : -o.x);
    r.y = fmaf(t, m.y, lbl ? o.y : -o.y);
  }
  return r;
}

__device__ __forceinline__ float2 rotd(float2 m, float t, int f, int lbl) {
  float2 r;
  if (f == 4) {        // RZ /c
    float tt = lbl ? -t : t;
    r.x = fmaf( tt, m.y, m.x);  r.y = fmaf(-tt, m.x, m.y);
  } else {             // RZ /s
    r.x = fmaf(t, m.x, lbl ? -m.y : m.y);
    r.y = fmaf(t, m.y, lbl ?  m.x : -m.x);
  }
  return r;
}

// Local amp index i: 14 bits; local bit k <-> qubit (14 - k) (qubits 1..14).
// Qubit 0 <-> cluster rank. Class = (q0 label, q1).
__global__ void __launch_bounds__(NTHREADS, 1) __cluster_dims__(2, 1, 1)
qdarts_kernel(const float* __restrict__ x, const float* __restrict__ Pm,
              const float* __restrict__ Qm, const float* __restrict__ rotp_,
              const float* __restrict__ gum, float* __restrict__ out)
{
  extern __shared__ float2 SM[];   // NLOC float2, LINEAR layout

  __shared__ float st_t[N_LAYERS * N_QUBITS];
  __shared__ int   st_f[N_LAYERS * N_QUBITS];
  __shared__ float st_s[N_LAYERS * N_QUBITS];
  __shared__ float sw[N_QUBITS][2];
  __shared__ float sred[4];
  __shared__ float sS2;

  cg::cluster_group cluster = cg::this_cluster();
  const int tid  = threadIdx.x;
  const int b    = blockIdx.x >> 1;
  const int rank = blockIdx.x & 1;
  const int lane = tid & 31;

  // ---- Gate selection: argmax(P@Q + gumbel); store (t, variant, scale). ----
  if (tid < N_LAYERS * N_QUBITS) {
    const int ix = tid;
    float best = -1e30f; int gb = 0;
#pragma unroll
    for (int gg = 0; gg < 3; gg++) {
      float logit = 0.f;
#pragma unroll
      for (int k = 0; k < 4; k++)
        logit += Pm[ix * 4 + k] * Qm[(ix * 4 + k) * 3 + gg];
      float v = logit + gum[ix * 3 + gg];
      if (v > best) { best = v; gb = gg; }
    }
    float sv, cv;
    sincosf(0.5f * rotp_[ix], &sv, &cv);
    const bool formB = fabsf(sv) > fabsf(cv);
    st_f[ix] = gb * 2 + (formB ? 1 : 0);
    st_t[ix] = formB ? __fdividef(cv, sv) : __fdividef(sv, cv);
    st_s[ix] = formB ? sv : cv;
  }
  if (tid < N_QUBITS) {
    float sv, cv;
    sincosf(0.5f * x[b * N_QUBITS + tid], &sv, &cv);
    sw[tid][0] = cv; sw[tid][1] = sv;
  }
  if (tid < 4) sred[tid] = 0.f;
  __syncthreads();

  if (tid == 0) {
    float pr = 1.f;
#pragma unroll 1
    for (int i = 0; i < N_LAYERS * N_QUBITS; i++) pr *= st_s[i];
    sS2 = pr * pr;
  }

  // Composed lane permutation for CNOT chain (10,11)(11,12)(12,13)(13,14)
  // on lane bits 4..0 (q10..q14): src bit k = lane_k ^ lane_{k+1}, k=0..3.
  int t_ = lane;
  t_ ^= ((t_ >> 1) & 1);        // C(13,14)
  t_ ^= ((t_ >> 2) & 1) << 1;   // C(12,13)
  t_ ^= ((t_ >> 3) & 1) << 2;   // C(11,12)
  t_ ^= ((t_ >> 4) & 1) << 3;   // C(10,11)
  const int srcE = t_;
  const int srcO = t_ ^ 16;     // C(9,10): ctrl q9 = reg bit0 (odd jb)

  float ps = 0.f; int pcls = 0;
  const int  tb9 = (tid >> 9) & 1;    // q5 label of this thread's amps (sweep A)
  const bool odd = (tid & 1) != 0;    // q14 (amp bit0) — CNOT(14,0) control

#pragma unroll 1
  for (int l = 0; l < N_LAYERS; l++) {
    const int g0 = l * N_QUBITS;
    float2 a[16];

    // ======== Sweep A: amp = (j<<10)|tid; reg j = amp bits 13..10 (q1..q4) ====
    // R_q0 and R_q5 applied as pair-on-load; CNOT(14,0) of layer l-1 fused.
    {
      const float t0 = st_t[g0];     const int f0 = st_f[g0];
      const float t5 = st_t[g0 + 5]; const int f5 = st_f[g0 + 5];
      const bool q0d = (f0 >= 4), q5d = (f5 >= 4);

      if (l == 0) {
        float pref = 1.f;
#pragma unroll
        for (int q = 6; q < 15; q++) pref *= sw[q][(tid >> (14 - q)) & 1];
        const float w5m = sw[5][tb9], w5o = sw[5][tb9 ^ 1];
        const float w0m = sw[0][rank], w0o = sw[0][rank ^ 1];
#pragma unroll
        for (int j = 0; j < 16; j++) {
          float f = pref;
#pragma unroll
          for (int q = 1; q < 5; q++) f *= sw[q][(j >> (4 - q)) & 1];
          float2 mv, ov;
          if (q5d) {
            mv = rotd(make_float2(f * w5m * w0m, 0.f), t5, f5, tb9);
            ov = rotd(make_float2(f * w5m * w0o, 0.f), t5, f5, tb9);
          } else {
            mv = rotp(make_float2(f * w5m * w0m, 0.f),
                      make_float2(f * w5o * w0m, 0.f), t5, f5, tb9);
            ov = rotp(make_float2(f * w5m * w0o, 0.f),
                      make_float2(f * w5o * w0o, 0.f), t5, f5, tb9);
          }
          a[j] = q0d ? rotd(mv, t0, f0, rank) : rotp(mv, ov, t0, f0, rank);
        }
      } else {
        const float2* pg = g_xchg + ((size_t)(b * 2 + ((l - 1) & 1)) * 2
                                     + (rank ^ 1)) * NLOC;
        if (q0d) {          // R_q0 diagonal: only the post-CNOT own chain.
          if (q5d) {
#pragma unroll
            for (int j = 0; j < 16; j++) {
              const int i = (j << 10) | tid;
              float2 v = odd ? __ldcg(&pg[i]) : SM[i];
              a[j] = rotd(rotd(v, t5, f5, tb9), t0, f0, rank);
            }
          } else {
#pragma unroll
            for (int j = 0; j < 16; j++) {
              const int i = (j << 10) | tid, i2 = i ^ 512;
              float2 v  = odd ? __ldcg(&pg[i])  : SM[i];
              float2 v2 = odd ? __ldcg(&pg[i2]) : SM[i2];
              a[j] = rotd(rotp(v, v2, t5, f5, tb9), t0, f0, rank);
            }
          }
        } else {
          if (q5d) {
#pragma unroll
            for (int j = 0; j < 16; j++) {
              const int i = (j << 10) | tid;
              float2 sA = SM[i], gA = __ldcg(&pg[i]);
              float2 mv = rotd(odd ? gA : sA, t5, f5, tb9);
              float2 ov = rotd(odd ? sA : gA, t5, f5, tb9);
              a[j] = rotp(mv, ov, t0, f0, rank);
            }
          } else {
#pragma unroll
            for (int j = 0; j < 16; j++) {
              const int i = (j << 10) | tid, i2 = i ^ 512;
              float2 sA = SM[i],  gA = __ldcg(&pg[i]);
              float2 sB = SM[i2], gB = __ldcg(&pg[i2]);
              float2 mv = rotp(odd ? gA : sA, odd ? gB : sB, t5, f5, tb9);
              float2 ov = rotp(odd ? sA : gA, odd ? sB : gB, t5, f5, tb9);
              a[j] = rotp(mv, ov, t0, f0, rank);
            }
          }
        }
      }
      rotfac16<3>(a, st_t[g0 + 1], st_f[g0 + 1]);  // R_q1
      rotfac16<2>(a, st_t[g0 + 2], st_f[g0 + 2]);  // R_q2
      rotfac16<1>(a, st_t[g0 + 3], st_f[g0 + 3]);  // R_q3
      rotfac16<0>(a, st_t[g0 + 4], st_f[g0 + 4]);  // R_q4
      // CNOT(0,1): ctrl q0 = rank (uniform) -> swap reg bit3.
      if (rank) {
#pragma unroll
        for (int j = 0; j < 8; j++) {
          float2 t2 = a[j]; a[j] = a[j | 8]; a[j | 8] = t2;
        }
      }
      cnotl16<3, 2>(a);  // CNOT(1,2)
      cnotl16<2, 1>(a);  // CNOT(2,3)
      cnotl16<1, 0>(a);  // CNOT(3,4)
      // CNOT(4,5): ctrl q4 = reg bit0, tgt q5 = amp bit9 -> store transform.
#pragma unroll
      for (int j = 0; j < 16; j++)
        SM[((j << 10) | tid) ^ ((j & 1) << 9)] = a[j];
    }
    __syncthreads();

    // ======== Sweep B: amp = (w5<<9)|(jb<<5)|lane ========
    // reg jb = amp bits 8..5 (q6..q9); lane = amp bits 4..0 (q10..q14).
    {
      const int w5 = tid >> 5;
      const int base = (w5 << 9) | lane;
#pragma unroll
      for (int j = 0; j < 16; j++) a[j] = SM[base | (j << 5)];
      // Rotations q6..q9 (register bits 3..0)
      rotfac16<3>(a, st_t[g0 + 6], st_f[g0 + 6]);
      rotfac16<2>(a, st_t[g0 + 7], st_f[g0 + 7]);
      rotfac16<1>(a, st_t[g0 + 8], st_f[g0 + 8]);
      rotfac16<0>(a, st_t[g0 + 9], st_f[g0 + 9]);
      // Rotations q10..q14 (lane bits 4..0)
      rot_lane_fac16<4>(a, st_t[g0 + 10], st_f[g0 + 10], lane);
      rot_lane_fac16<3>(a, st_t[g0 + 11], st_f[g0 + 11], lane);
      rot_lane_fac16<2>(a, st_t[g0 + 12], st_f[g0 + 12], lane);
      rot_lane_fac16<1>(a, st_t[g0 + 13], st_f[g0 + 13], lane);
      rot_lane_fac16<0>(a, st_t[g0 + 14], st_f[g0 + 14], lane);
      // CNOT(5,6): ctrl q5 = amp bit9 = w5 bit0; tgt q6 = reg bit3.
      xcond16<3>(a, (w5 & 1) != 0);
      cnotl16<3, 2>(a);  // CNOT(6,7)
      cnotl16<2, 1>(a);  // CNOT(7,8)
      cnotl16<1, 0>(a);  // CNOT(8,9)
      // CNOT(9,10)+(10,11)+(11,12)+(12,13)+(13,14): composed lane perm.
#pragma unroll
      for (int j = 0; j < 16; j++) {
        const int src = (j & 1) ? srcO : srcE;
        a[j].x = __shfl_sync(0xffffffffu, a[j].x, src);
        a[j].y = __shfl_sync(0xffffffffu, a[j].y, src);
      }
      // CNOT(14,0): physical, fused into next layer's sweep-A loads
      // (or into the class remap below for the last layer).

      if (l < N_LAYERS - 1) {
        float2* xw = g_xchg + ((size_t)(b * 2 + (l & 1)) * 2 + rank) * NLOC;
#pragma unroll
        for (int j = 0; j < 16; j++) {
          const int i = base | (j << 5);
          SM[i] = a[j];
          xw[i] = a[j];
        }
        cluster.sync();
      } else {
        // |amp|^2 class reduction with CNOT(14,0) fold.
        // ctrl q14 = amp bit0 = lane bit0; class = (q0 label, q1);
        // q1 = amp bit13 = w5 bit4 = tid bit9.
        float p = 0.f;
#pragma unroll
        for (int j = 0; j < 16; j++)
          p = fmaf(a[j].x, a[j].x, fmaf(a[j].y, a[j].y, p));
        ps = p;
        pcls = ((((lane & 1) ? (rank ^ 1) : rank) << 1) | tb9);
      }
    }
  }

  // ---- Reduce: parity-preserving warp reduce -> CTA shared -> cross-CTA ----
#pragma unroll
  for (int o = 16; o >= 2; o >>= 1)
    ps += __shfl_xor_sync(0xffffffffu, ps, o);
  if (lane < 2) atomicAdd(&sred[pcls], ps);
  __syncthreads();

  if (rank == 1 && tid < 4) {
    float* dst = cluster.map_shared_rank(sred, 0);
    atomicAdd(dst + tid, sred[tid]);
  }
  cluster.sync();
  if (rank == 0 && tid < 4) out[b * 4 + tid] = sred[tid] * sS2;
}

extern "C" void kernel_launch(void* const* d_in, const int* in_sizes, int n_in,
                              void* d_out, int out_size) {
  const float* x    = (const float*)d_in[0];
  const float* P    = (const float*)d_in[1];
  const float* Q    = (const float*)d_in[2];
  const float* rotp = (const float*)d_in[3];
  const float* gum  = (const float*)d_in[4];
  cudaFuncSetAttribute(qdarts_kernel,
                       cudaFuncAttributeMaxDynamicSharedMemorySize,
                       (int)SMEM_BYTES);
  qdarts_kernel<<<BATCHN * 2, NTHREADS, SMEM_BYTES>>>(x, P, Q, rotp, gum,
                                                      (float*)d_out);
}